// round 5
// baseline (speedup 1.0000x reference)
#include <cuda_runtime.h>
#include <math.h>

#define BATCH 256
#define TT    257
#define HID   512
#define EMB   256
#define CF    512
#define HW    64
#define NMIX  20
#define KP    1040            // gates K padded: 512(att)+5(pt)+512(h)=1029 -> 1040
#define OUTROWS (BATCH*TT)    // 65792
#define OFF   (OUTROWS*NMIX)  // 1315840

// ---------------- device scratch (no allocs allowed) ----------------
__device__ float g_WgT [KP*2048];      // gates weights, K-major  (8.5 MB)
__device__ float g_WkT [4608*256];     // conv weights, K-major   (4.7 MB)
__device__ float g_WchT[512*256];      // W_conv_h transposed
__device__ float g_WpT [512*128];      // W_fc_params transposed (padded to 128)
__device__ float g_orgT[BATCH*HW*CF];  // backbone transposed to [b][hw][c] (33.5 MB)
__device__ float g_xem [BATCH*HW*EMB]; // conv output [b][hw][e]  (16.8 MB)
__device__ float g_hbuf[2][BATCH*HID];
__device__ float g_c   [BATCH*HID];
__device__ float g_att [BATCH*CF];

__device__ __forceinline__ float sigm(float x) { return 1.f / (1.f + expf(-x)); }

// ---------------- one-time pack / transpose ----------------
__global__ void pack_kernel(const float* __restrict__ Wih, const float* __restrict__ Whh,
                            const float* __restrict__ Wch, const float* __restrict__ Wp,
                            const float* __restrict__ Kc,  const float* __restrict__ bb)
{
    int i = blockIdx.x * 256 + threadIdx.x;
    if (i < KP*2048) {                       // WgT[k][j]
        int k = i / 2048, j = i - k*2048;
        float v = 0.f;
        if (k < 517)       v = Wih[j*517 + k];
        else if (k < 1029) v = Whh[j*512 + (k-517)];
        g_WgT[i] = v;
    }
    if (i < 4608*256) {                      // WkT[c*9+tap][e]
        int k = i >> 8, e = i & 255;
        int c = k / 9, tap = k - c*9;
        g_WkT[i] = Kc[(e*512 + c)*9 + tap];
    }
    if (i < 512*256) {                       // WchT[k][e]
        int k = i >> 8, e = i & 255;
        g_WchT[i] = Wch[e*512 + k];
    }
    if (i < 512*128) {                       // WpT[k][j]
        int k = i >> 7, j = i & 127;
        g_WpT[i] = (j < 123) ? Wp[j*512 + k] : 0.f;
    }
    if (i < BATCH*HW*CF) {                   // orgT[b][hw][c]
        int c = i & 511; int hw = (i >> 9) & 63; int b = i >> 15;
        g_orgT[i] = bb[(b*CF + c)*HW + hw];
    }
}

// ---------------- h0/c0 = tanh(z @ W_fc_hc^T + b) ----------------
__global__ void init_hc_kernel(const float* __restrict__ z, const float* __restrict__ Whc,
                               const float* __restrict__ bhc)
{
    __shared__ float sh_z[4*128];
    int tid = threadIdx.x;                   // 256
    int b0 = blockIdx.x * 4;
    for (int i = tid; i < 512; i += 256) sh_z[i] = z[b0*128 + i];
    __syncthreads();
    for (int jj = tid; jj < 1024; jj += 256) {
        float a0 = 0.f, a1 = 0.f, a2 = 0.f, a3 = 0.f;
        for (int k = 0; k < 128; k++) {
            float w = Whc[jj*128 + k];
            a0 += w * sh_z[k];       a1 += w * sh_z[128 + k];
            a2 += w * sh_z[256 + k]; a3 += w * sh_z[384 + k];
        }
        float bv = bhc[jj];
        float v[4] = { tanhf(a0+bv), tanhf(a1+bv), tanhf(a2+bv), tanhf(a3+bv) };
        #pragma unroll
        for (int b = 0; b < 4; b++) {
            if (jj < 512) g_hbuf[0][(b0+b)*512 + jj]      = v[b];
            else          g_c     [(b0+b)*512 + (jj-512)] = v[b];
        }
    }
}

// ---------------- conv3x3 SAME as implicit GEMM: xem[m][e], M=B*HW, K=4608 ----------------
__global__ void conv_kernel(const float* __restrict__ bb, const float* __restrict__ bconv)
{
    __shared__ float As[16*68];
    __shared__ float Bs[16*64];
    int tid = threadIdx.x;
    int m0 = blockIdx.x * 64;
    int n0 = blockIdx.y * 64;
    int tx = tid & 15, ty = tid >> 4;
    float acc[4][4] = {};

    int lmm = tid & 63, lkb = tid >> 6;      // loader roles
    int m = m0 + lmm;
    int bidx = m >> 6, pix = m & 63, py = pix >> 3, px = pix & 7;

    for (int kt = 0; kt < 4608; kt += 16) {
        #pragma unroll
        for (int i = 0; i < 4; i++) {        // A tile (patches)
            int kk = lkb*4 + i; int k = kt + kk;
            int c = k / 9, tap = k - c*9;
            int dy = tap / 3, dx = tap - dy*3;
            int yy = py + dy - 1, xx = px + dx - 1;
            float v = 0.f;
            if (yy >= 0 && yy < 8 && xx >= 0 && xx < 8)
                v = bb[((bidx*CF + c) << 6) + yy*8 + xx];
            As[kk*68 + lmm] = v;
        }
        #pragma unroll
        for (int i = 0; i < 4; i++) {        // B tile (weights, coalesced)
            int kk = lkb*4 + i;
            Bs[kk*64 + lmm] = g_WkT[(kt+kk)*256 + n0 + lmm];
        }
        __syncthreads();
        #pragma unroll
        for (int kk = 0; kk < 16; kk++) {
            float4 a  = *(const float4*)&As[kk*68 + ty*4];
            float4 bv = *(const float4*)&Bs[kk*64 + tx*4];
            acc[0][0] += a.x*bv.x; acc[0][1] += a.x*bv.y; acc[0][2] += a.x*bv.z; acc[0][3] += a.x*bv.w;
            acc[1][0] += a.y*bv.x; acc[1][1] += a.y*bv.y; acc[1][2] += a.y*bv.z; acc[1][3] += a.y*bv.w;
            acc[2][0] += a.z*bv.x; acc[2][1] += a.z*bv.y; acc[2][2] += a.z*bv.z; acc[2][3] += a.z*bv.w;
            acc[3][0] += a.w*bv.x; acc[3][1] += a.w*bv.y; acc[3][2] += a.w*bv.z; acc[3][3] += a.w*bv.w;
        }
        __syncthreads();
    }
    int e0 = n0 + tx*4;
    float b0v = bconv[e0], b1v = bconv[e0+1], b2v = bconv[e0+2], b3v = bconv[e0+3];
    #pragma unroll
    for (int r = 0; r < 4; r++) {
        int mm = m0 + ty*4 + r;
        float4 o;
        o.x = acc[r][0] + b0v; o.y = acc[r][1] + b1v;
        o.z = acc[r][2] + b2v; o.w = acc[r][3] + b3v;
        *(float4*)&g_xem[mm*256 + e0] = o;
    }
}

// ---------------- per-step: g_em + tanh attention + softmax + att (4 batches / block) ----------------
__global__ void attn_kernel(const float* __restrict__ bconvh, const float* __restrict__ watt,
                            const float* __restrict__ batt, int t)
{
    __shared__ float sh_h[4*512];
    __shared__ float sh_gem[4*256];
    __shared__ float sh_w[256];
    __shared__ float sh_sc[4*64];
    int tid = threadIdx.x;                   // 256
    int b0 = blockIdx.x * 4;
    const float* hcur = g_hbuf[t & 1];

    for (int i = tid; i < 2048; i += 256) sh_h[i] = hcur[b0*512 + i];
    sh_w[tid] = watt[tid];
    __syncthreads();

    { // g_em = h @ WchT + b  (4 batches share weight stream)
        float a0=0.f, a1=0.f, a2=0.f, a3=0.f;
        for (int k = 0; k < 512; k++) {
            float w = g_WchT[k*256 + tid];
            a0 += w*sh_h[k]; a1 += w*sh_h[512+k]; a2 += w*sh_h[1024+k]; a3 += w*sh_h[1536+k];
        }
        float bv = bconvh[tid];
        sh_gem[tid] = a0+bv; sh_gem[256+tid] = a1+bv; sh_gem[512+tid] = a2+bv; sh_gem[768+tid] = a3+bv;
    }
    __syncthreads();

    int wid = tid >> 5, lane = tid & 31;
    float bav = batt[0];
    for (int p = wid; p < 256; p += 8) {     // scores
        int bb = p >> 6, hw = p & 63;
        const float* xr = &g_xem[((b0+bb)*64 + hw)*256];
        const float* ge = &sh_gem[bb*256];
        float s = 0.f;
        for (int e = lane; e < 256; e += 32)
            s += sh_w[e] * tanhf(xr[e] + ge[e]);
        #pragma unroll
        for (int o = 16; o; o >>= 1) s += __shfl_xor_sync(0xffffffffu, s, o);
        if (lane == 0) sh_sc[bb*64 + hw] = s + bav;
    }
    __syncthreads();

    if (wid < 4) {                           // softmax over 64
        int bb = wid;
        float v0 = sh_sc[bb*64 + lane], v1 = sh_sc[bb*64 + 32 + lane];
        float m = fmaxf(v0, v1);
        #pragma unroll
        for (int o = 16; o; o >>= 1) m = fmaxf(m, __shfl_xor_sync(0xffffffffu, m, o));
        float e0 = expf(v0 - m), e1 = expf(v1 - m);
        float s = e0 + e1;
        #pragma unroll
        for (int o = 16; o; o >>= 1) s += __shfl_xor_sync(0xffffffffu, s, o);
        float inv = 1.f / s;
        sh_sc[bb*64 + lane] = e0*inv; sh_sc[bb*64 + 32 + lane] = e1*inv;
    }
    __syncthreads();

    for (int c = tid; c < 512; c += 256) {   // att = alpha @ orgfeat
        float a[4] = {0.f,0.f,0.f,0.f};
        for (int hw = 0; hw < 64; hw++) {
            #pragma unroll
            for (int bb = 0; bb < 4; bb++)
                a[bb] += sh_sc[bb*64 + hw] * g_orgT[((b0+bb)*64 + hw)*512 + c];
        }
        #pragma unroll
        for (int bb = 0; bb < 4; bb++)
            g_att[(b0+bb)*512 + c] = a[bb];
    }
}

// ---------------- per-step: gates GEMM (M=256,N=2048,K=1029pad) + LSTM cell ----------------
// Block covers 32 rows x 16 units; "unit" u owns gate columns {u, u+512, u+1024, u+1536}.
__global__ void gates_kernel(const float* __restrict__ bih, const float* __restrict__ bhh,
                             const float* __restrict__ sketch, int t)
{
    __shared__ float As[16*34];              // [kk][mm], padded
    __shared__ float Bs[16*16*4];            // [kk][unit][gate]
    int tid = threadIdx.x;                   // 256
    int m0 = blockIdx.x * 32;
    int u0 = blockIdx.y * 16;
    int tx = tid & 15, ty = tid >> 4;
    const float* hcur  = g_hbuf[t & 1];
    float*       hnext = g_hbuf[(t + 1) & 1];
    float acc[2][4] = {};

    int lmm = tid >> 3;                      // 0..31
    int lkq = (tid & 7) * 2;                 // 0,2,..,14
    int lrow = m0 + lmm;

    for (int kt = 0; kt < KP; kt += 16) {
        #pragma unroll
        for (int i = 0; i < 2; i++) {        // A = concat(att, pt, h) built on the fly
            int kk = lkq + i; int k = kt + kk;
            float v;
            if (k < 512)       v = g_att[lrow*512 + k];
            else if (k < 517)  { int kp = k - 512;
                                 v = (t == 0) ? (kp == 2 ? 1.f : 0.f)
                                              : sketch[((t-1)*BATCH + lrow)*5 + kp]; }
            else if (k < 1029) v = hcur[lrow*512 + (k - 517)];
            else               v = 0.f;
            As[kk*34 + lmm] = v;
        }
        #pragma unroll
        for (int r = 0; r < 4; r++) {        // B tile from packed WgT
            int idx = tid + r*256;
            int kk = idx >> 6; int rem = idx & 63; int gg = rem >> 4; int ul = rem & 15;
            Bs[(kk*16 + ul)*4 + gg] = g_WgT[(kt+kk)*2048 + gg*512 + u0 + ul];
        }
        __syncthreads();
        #pragma unroll
        for (int kk = 0; kk < 16; kk++) {
            float2 a  = *(const float2*)&As[kk*34 + ty*2];
            float4 bv = *(const float4*)&Bs[(kk*16 + tx)*4];
            acc[0][0] += a.x*bv.x; acc[0][1] += a.x*bv.y; acc[0][2] += a.x*bv.z; acc[0][3] += a.x*bv.w;
            acc[1][0] += a.y*bv.x; acc[1][1] += a.y*bv.y; acc[1][2] += a.y*bv.z; acc[1][3] += a.y*bv.w;
        }
        __syncthreads();
    }

    int u = u0 + tx;
    float bs0 = bih[u]        + bhh[u];
    float bs1 = bih[512 + u]  + bhh[512 + u];
    float bs2 = bih[1024 + u] + bhh[1024 + u];
    float bs3 = bih[1536 + u] + bhh[1536 + u];
    #pragma unroll
    for (int r = 0; r < 2; r++) {
        int row = m0 + ty*2 + r;
        float iv = acc[r][0] + bs0;
        float fv = acc[r][1] + bs1;
        float gv = acc[r][2] + bs2;
        float ov = acc[r][3] + bs3;
        float co = g_c[row*512 + u];
        float cn = sigm(fv)*co + sigm(iv)*tanhf(gv);
        float hn = sigm(ov)*tanhf(cn);
        g_c[row*512 + u] = cn;
        hnext[row*512 + u] = hn;
    }
}

// ---------------- per-step: output head y = h @ Wp^T + postprocess, scattered to d_out ----------------
__global__ void head_kernel(const float* __restrict__ bfc, float* __restrict__ out, int t)
{
    __shared__ float sh_h[4*512];
    __shared__ float sh_y[4*128];
    __shared__ float sh_mx[4], sh_inv[4];
    int tid = threadIdx.x;                   // 128
    int b0 = blockIdx.x * 4;
    const float* hn = g_hbuf[(t + 1) & 1];

    for (int i = tid; i < 2048; i += 128) sh_h[i] = hn[b0*512 + i];
    __syncthreads();

    float a0=0.f, a1=0.f, a2=0.f, a3=0.f;
    for (int k = 0; k < 512; k++) {
        float w = g_WpT[k*128 + tid];
        a0 += w*sh_h[k]; a1 += w*sh_h[512+k]; a2 += w*sh_h[1024+k]; a3 += w*sh_h[1536+k];
    }
    float bias = (tid < 123) ? bfc[tid] : 0.f;
    sh_y[tid] = a0+bias; sh_y[128+tid] = a1+bias; sh_y[256+tid] = a2+bias; sh_y[384+tid] = a3+bias;
    __syncthreads();

    if (tid < 4) {                           // pi softmax stats
        float m = -1e30f;
        for (int i = 3; i < 23; i++) m = fmaxf(m, sh_y[tid*128 + i]);
        float s = 0.f;
        for (int i = 3; i < 23; i++) s += expf(sh_y[tid*128 + i] - m);
        sh_mx[tid] = m; sh_inv[tid] = 1.f / s;
    }
    __syncthreads();

    if (tid < 123) {
        #pragma unroll
        for (int bb = 0; bb < 4; bb++) {
            int row = (b0 + bb)*257 + t;
            float y = sh_y[bb*128 + tid];
            if (tid < 3)        out[6*OFF + row*3 + tid] = y;                         // pen logits
            else if (tid < 23)  out[          row*20 + (tid-3)]   = expf(y - sh_mx[bb]) * sh_inv[bb];
            else if (tid < 43)  out[1*OFF +  row*20 + (tid-23)]  = y;                 // mu1
            else if (tid < 63)  out[2*OFF +  row*20 + (tid-43)]  = y;                 // mu2
            else if (tid < 83)  out[3*OFF +  row*20 + (tid-63)]  = expf(y);           // s1
            else if (tid < 103) out[4*OFF +  row*20 + (tid-83)]  = expf(y);           // s2
            else                out[5*OFF +  row*20 + (tid-103)] = tanhf(y);          // corr
        }
    }
}

// ---------------- launcher ----------------
extern "C" void kernel_launch(void* const* d_in, const int* in_sizes, int n_in,
                              void* d_out, int out_size)
{
    const float* backbone = (const float*)d_in[0];
    const float* z        = (const float*)d_in[1];
    const float* sketch   = (const float*)d_in[2];
    const float* Whc      = (const float*)d_in[3];
    const float* bhc      = (const float*)d_in[4];
    const float* Wch      = (const float*)d_in[5];
    const float* bch      = (const float*)d_in[6];
    const float* Kconv    = (const float*)d_in[7];
    const float* bconvf   = (const float*)d_in[8];
    const float* Watt     = (const float*)d_in[9];
    const float* batt     = (const float*)d_in[10];
    const float* Wih      = (const float*)d_in[11];
    const float* Whh      = (const float*)d_in[12];
    const float* bih      = (const float*)d_in[13];
    const float* bhh      = (const float*)d_in[14];
    const float* Wp       = (const float*)d_in[15];
    const float* bfc      = (const float*)d_in[16];
    float* out = (float*)d_out;
    (void)in_sizes; (void)n_in; (void)out_size;

    pack_kernel<<<32768, 256>>>(Wih, Whh, Wch, Wp, Kconv, backbone);
    init_hc_kernel<<<64, 256>>>(z, Whc, bhc);
    conv_kernel<<<dim3(256, 4), 256>>>(backbone, bconvf);

    for (int t = 0; t < TT; t++) {
        attn_kernel<<<64, 256>>>(bch, Watt, batt, t);
        gates_kernel<<<dim3(8, 32), 256>>>(bih, bhh, sketch, t);
        head_kernel<<<64, 128>>>(bfc, out, t);
    }
}

// round 9
// speedup vs baseline: 1.6738x; 1.6738x over previous
#include <cuda_runtime.h>
#include <math.h>

#define BATCH 256
#define TT    257
#define HID   512
#define EMB   256
#define CF    512
#define HW    64
#define NMIX  20
#define KP    1040            // gates K padded: 512(att)+5(pt)+512(h)=1029 -> 1040
#define OUTROWS (BATCH*TT)    // 65792
#define OFF   (OUTROWS*NMIX)  // 1315840

// ---------------- device scratch (no allocs allowed) ----------------
__device__ float g_WgT [KP*2048];      // gates weights, K-major  (8.5 MB)
__device__ float g_WkT [4608*256];     // conv weights, K-major   (4.7 MB)
__device__ float g_WchT[512*256];      // W_conv_h transposed
__device__ float g_WpT [512*128];      // W_fc_params transposed (padded to 128)
__device__ float g_orgT[BATCH*HW*CF];  // backbone transposed to [b][hw][c] (33.5 MB)
__device__ float g_xem [BATCH*HW*EMB]; // conv output [b][hw][e]  (16.8 MB)
__device__ float g_gem [BATCH*EMB];    // per-step g_em
__device__ float g_hbuf[2][BATCH*HID];
__device__ float g_c   [BATCH*HID];
__device__ float g_att [BATCH*CF];

__device__ __forceinline__ float sigm(float x) { return 1.f / (1.f + expf(-x)); }
__device__ __forceinline__ float ftanh(float x) {
    float y; asm("tanh.approx.f32 %0, %1;" : "=f"(y) : "f"(x)); return y;
}

// ---------------- one-time pack / transpose ----------------
__global__ void pack_kernel(const float* __restrict__ Wih, const float* __restrict__ Whh,
                            const float* __restrict__ Wch, const float* __restrict__ Wp,
                            const float* __restrict__ Kc,  const float* __restrict__ bb)
{
    int i = blockIdx.x * 256 + threadIdx.x;
    if (i < KP*2048) {                       // WgT[k][j]
        int k = i / 2048, j = i - k*2048;
        float v = 0.f;
        if (k < 517)       v = Wih[j*517 + k];
        else if (k < 1029) v = Whh[j*512 + (k-517)];
        g_WgT[i] = v;
    }
    if (i < 4608*256) {                      // WkT[c*9+tap][e]
        int k = i >> 8, e = i & 255;
        int c = k / 9, tap = k - c*9;
        g_WkT[i] = Kc[(e*512 + c)*9 + tap];
    }
    if (i < 512*256) {                       // WchT[k][e]
        int k = i >> 8, e = i & 255;
        g_WchT[i] = Wch[e*512 + k];
    }
    if (i < 512*128) {                       // WpT[k][j]
        int k = i >> 7, j = i & 127;
        g_WpT[i] = (j < 123) ? Wp[j*512 + k] : 0.f;
    }
    if (i < BATCH*HW*CF) {                   // orgT[b][hw][c]
        int c = i & 511; int hw = (i >> 9) & 63; int b = i >> 15;
        g_orgT[i] = bb[(b*CF + c)*HW + hw];
    }
}

// ---------------- h0/c0 = tanh(z @ W_fc_hc^T + b) ----------------
__global__ void init_hc_kernel(const float* __restrict__ z, const float* __restrict__ Whc,
                               const float* __restrict__ bhc)
{
    __shared__ float sh_z[4*128];
    int tid = threadIdx.x;                   // 256
    int b0 = blockIdx.x * 4;
    for (int i = tid; i < 512; i += 256) sh_z[i] = z[b0*128 + i];
    __syncthreads();
    for (int jj = tid; jj < 1024; jj += 256) {
        float a0 = 0.f, a1 = 0.f, a2 = 0.f, a3 = 0.f;
        for (int k = 0; k < 128; k++) {
            float w = Whc[jj*128 + k];
            a0 += w * sh_z[k];       a1 += w * sh_z[128 + k];
            a2 += w * sh_z[256 + k]; a3 += w * sh_z[384 + k];
        }
        float bv = bhc[jj];
        float v[4] = { tanhf(a0+bv), tanhf(a1+bv), tanhf(a2+bv), tanhf(a3+bv) };
        #pragma unroll
        for (int b = 0; b < 4; b++) {
            if (jj < 512) g_hbuf[0][(b0+b)*512 + jj]      = v[b];
            else          g_c     [(b0+b)*512 + (jj-512)] = v[b];
        }
    }
}

// ---------------- conv3x3 SAME as implicit GEMM: xem[m][e], M=B*HW, K=4608 ----------------
__global__ void conv_kernel(const float* __restrict__ bb, const float* __restrict__ bconv)
{
    __shared__ float As[16*68];
    __shared__ float Bs[16*64];
    int tid = threadIdx.x;
    int m0 = blockIdx.x * 64;
    int n0 = blockIdx.y * 64;
    int tx = tid & 15, ty = tid >> 4;
    float acc[4][4] = {};

    int lmm = tid & 63, lkb = tid >> 6;      // loader roles
    int m = m0 + lmm;
    int bidx = m >> 6, pix = m & 63, py = pix >> 3, px = pix & 7;

    for (int kt = 0; kt < 4608; kt += 16) {
        #pragma unroll
        for (int i = 0; i < 4; i++) {        // A tile (patches)
            int kk = lkb*4 + i; int k = kt + kk;
            int c = k / 9, tap = k - c*9;
            int dy = tap / 3, dx = tap - dy*3;
            int yy = py + dy - 1, xx = px + dx - 1;
            float v = 0.f;
            if (yy >= 0 && yy < 8 && xx >= 0 && xx < 8)
                v = bb[((bidx*CF + c) << 6) + yy*8 + xx];
            As[kk*68 + lmm] = v;
        }
        #pragma unroll
        for (int i = 0; i < 4; i++) {        // B tile (weights, coalesced)
            int kk = lkb*4 + i;
            Bs[kk*64 + lmm] = g_WkT[(kt+kk)*256 + n0 + lmm];
        }
        __syncthreads();
        #pragma unroll
        for (int kk = 0; kk < 16; kk++) {
            float4 a  = *(const float4*)&As[kk*68 + ty*4];
            float4 bv = *(const float4*)&Bs[kk*64 + tx*4];
            acc[0][0] += a.x*bv.x; acc[0][1] += a.x*bv.y; acc[0][2] += a.x*bv.z; acc[0][3] += a.x*bv.w;
            acc[1][0] += a.y*bv.x; acc[1][1] += a.y*bv.y; acc[1][2] += a.y*bv.z; acc[1][3] += a.y*bv.w;
            acc[2][0] += a.z*bv.x; acc[2][1] += a.z*bv.y; acc[2][2] += a.z*bv.z; acc[2][3] += a.z*bv.w;
            acc[3][0] += a.w*bv.x; acc[3][1] += a.w*bv.y; acc[3][2] += a.w*bv.z; acc[3][3] += a.w*bv.w;
        }
        __syncthreads();
    }
    int e0 = n0 + tx*4;
    float b0v = bconv[e0], b1v = bconv[e0+1], b2v = bconv[e0+2], b3v = bconv[e0+3];
    #pragma unroll
    for (int r = 0; r < 4; r++) {
        int mm = m0 + ty*4 + r;
        float4 o;
        o.x = acc[r][0] + b0v; o.y = acc[r][1] + b1v;
        o.z = acc[r][2] + b2v; o.w = acc[r][3] + b3v;
        *(float4*)&g_xem[mm*256 + e0] = o;
    }
}

// ---------------- gem device helper: g_em = h @ WchT + b (16 batches x 32 cols / block) ----
__device__ __forceinline__ void gem_block(const float* __restrict__ hsrc,
                                          const float* __restrict__ bconvh,
                                          float* sh_h, int bid, int tid)
{
    int bg = (bid >> 3) * 16;
    int cg = (bid & 7) * 32;

    for (int i = tid; i < 16*512; i += 256) sh_h[i] = hsrc[bg*512 + i];
    __syncthreads();

    int wid = tid >> 5, lane = tid & 31;
    int col = cg + lane;
    const float* h0 = &sh_h[(wid*2)*512];
    const float* h1 = &sh_h[(wid*2+1)*512];
    float a0 = 0.f, a1 = 0.f;
    #pragma unroll 8
    for (int k = 0; k < 512; k++) {
        float w = g_WchT[k*256 + col];
        a0 += w * h0[k];
        a1 += w * h1[k];
    }
    float bv = bconvh[col];
    g_gem[(bg + wid*2    )*256 + col] = a0 + bv;
    g_gem[(bg + wid*2 + 1)*256 + col] = a1 + bv;
}

// ---------------- pre-loop gem for t=0 ----------------
__global__ void gem0_kernel(const float* __restrict__ bconvh)
{
    __shared__ float sh_h[16*512];
    gem_block(g_hbuf[0], bconvh, sh_h, blockIdx.x, threadIdx.x);
}

// ---------------- per-step: tanh attention + softmax + att reduce (1 batch / block) -------
__global__ void attn_kernel(const float* __restrict__ watt, const float* __restrict__ batt,
                            int t)
{
    __shared__ float sh_gem[256];
    __shared__ float sh_w[256];
    __shared__ float sh_sc[64];
    int tid = threadIdx.x;                   // 256
    int b = blockIdx.x;

    sh_gem[tid] = g_gem[b*256 + tid];
    sh_w[tid]   = watt[tid];
    __syncthreads();

    int wid = tid >> 5, lane = tid & 31;
    float bav = batt[0];
    const float4* gem4 = (const float4*)sh_gem;
    const float4* w4   = (const float4*)sh_w;
    float4 gA = gem4[2*lane], gB = gem4[2*lane+1];
    float4 wA = w4[2*lane],   wB = w4[2*lane+1];

    #pragma unroll
    for (int hw = wid; hw < 64; hw += 8) {   // scores
        const float4* xr = (const float4*)&g_xem[(b*64 + hw)*256];
        float4 x0 = xr[2*lane], x1 = xr[2*lane+1];
        float s;
        s  = wA.x * ftanh(x0.x + gA.x);
        s += wA.y * ftanh(x0.y + gA.y);
        s += wA.z * ftanh(x0.z + gA.z);
        s += wA.w * ftanh(x0.w + gA.w);
        s += wB.x * ftanh(x1.x + gB.x);
        s += wB.y * ftanh(x1.y + gB.y);
        s += wB.z * ftanh(x1.z + gB.z);
        s += wB.w * ftanh(x1.w + gB.w);
        #pragma unroll
        for (int o = 16; o; o >>= 1) s += __shfl_xor_sync(0xffffffffu, s, o);
        if (lane == 0) sh_sc[hw] = s + bav;
    }
    __syncthreads();

    if (wid == 0) {                          // softmax over 64
        float v0 = sh_sc[lane], v1 = sh_sc[32 + lane];
        float m = fmaxf(v0, v1);
        #pragma unroll
        for (int o = 16; o; o >>= 1) m = fmaxf(m, __shfl_xor_sync(0xffffffffu, m, o));
        float e0 = expf(v0 - m), e1 = expf(v1 - m);
        float s = e0 + e1;
        #pragma unroll
        for (int o = 16; o; o >>= 1) s += __shfl_xor_sync(0xffffffffu, s, o);
        float inv = 1.f / s;
        sh_sc[lane] = e0*inv; sh_sc[32 + lane] = e1*inv;
    }
    __syncthreads();

    {                                        // att = alpha @ orgfeat  (2 cols / thread)
        const float* org = &g_orgT[b*64*512];
        float a0 = 0.f, a1 = 0.f;
        #pragma unroll 8
        for (int hw = 0; hw < 64; hw++) {
            float al = sh_sc[hw];
            a0 += al * org[hw*512 + tid];
            a1 += al * org[hw*512 + 256 + tid];
        }
        g_att[b*512 + tid]       = a0;
        g_att[b*512 + 256 + tid] = a1;
    }
}

// ---------------- per-step: gates GEMM (M=256,N=2048,K=1029pad) + LSTM cell ----------------
__global__ void gates_kernel(const float* __restrict__ bih, const float* __restrict__ bhh,
                             const float* __restrict__ sketch, int t)
{
    __shared__ float As[16*34];              // [kk][mm], padded
    __shared__ float Bs[16*16*4];            // [kk][unit][gate]
    int tid = threadIdx.x;                   // 256
    int m0 = blockIdx.x * 32;
    int u0 = blockIdx.y * 16;
    int tx = tid & 15, ty = tid >> 4;
    const float* hcur  = g_hbuf[t & 1];
    float*       hnext = g_hbuf[(t + 1) & 1];
    float acc[2][4] = {};

    int lmm = tid >> 3;                      // 0..31
    int lkq = (tid & 7) * 2;                 // 0,2,..,14
    int lrow = m0 + lmm;

    for (int kt = 0; kt < KP; kt += 16) {
        #pragma unroll
        for (int i = 0; i < 2; i++) {        // A = concat(att, pt, h) built on the fly
            int kk = lkq + i; int k = kt + kk;
            float v;
            if (k < 512)       v = g_att[lrow*512 + k];
            else if (k < 517)  { int kp = k - 512;
                                 v = (t == 0) ? (kp == 2 ? 1.f : 0.f)
                                              : sketch[((t-1)*BATCH + lrow)*5 + kp]; }
            else if (k < 1029) v = hcur[lrow*512 + (k - 517)];
            else               v = 0.f;
            As[kk*34 + lmm] = v;
        }
        #pragma unroll
        for (int r = 0; r < 4; r++) {        // B tile from packed WgT
            int idx = tid + r*256;
            int kk = idx >> 6; int rem = idx & 63; int gg = rem >> 4; int ul = rem & 15;
            Bs[(kk*16 + ul)*4 + gg] = g_WgT[(kt+kk)*2048 + gg*512 + u0 + ul];
        }
        __syncthreads();
        #pragma unroll
        for (int kk = 0; kk < 16; kk++) {
            float2 a  = *(const float2*)&As[kk*34 + ty*2];
            float4 bv = *(const float4*)&Bs[(kk*16 + tx)*4];
            acc[0][0] += a.x*bv.x; acc[0][1] += a.x*bv.y; acc[0][2] += a.x*bv.z; acc[0][3] += a.x*bv.w;
            acc[1][0] += a.y*bv.x; acc[1][1] += a.y*bv.y; acc[1][2] += a.y*bv.z; acc[1][3] += a.y*bv.w;
        }
        __syncthreads();
    }

    int u = u0 + tx;
    float bs0 = bih[u]        + bhh[u];
    float bs1 = bih[512 + u]  + bhh[512 + u];
    float bs2 = bih[1024 + u] + bhh[1024 + u];
    float bs3 = bih[1536 + u] + bhh[1536 + u];
    #pragma unroll
    for (int r = 0; r < 2; r++) {
        int row = m0 + ty*2 + r;
        float iv = acc[r][0] + bs0;
        float fv = acc[r][1] + bs1;
        float gv = acc[r][2] + bs2;
        float ov = acc[r][3] + bs3;
        float co = g_c[row*512 + u];
        float cn = sigm(fv)*co + sigm(iv)*tanhf(gv);
        float hn = sigm(ov)*tanhf(cn);
        g_c[row*512 + u] = cn;
        hnext[row*512 + u] = hn;
    }
}

// ---------------- per-step fused: head(t) [blocks 128..255] + gem(t+1) [blocks 0..127] ----
// Both read hbuf[(t+1)&1], written by gates(t). Independent outputs.
__global__ void head_gem_kernel(const float* __restrict__ bfc, float* __restrict__ out,
                                const float* __restrict__ bconvh, int t)
{
    __shared__ float sh_h[16*512];           // gem branch (32 KB)
    __shared__ float sh_h2[2*512];           // head branch
    __shared__ float sh_y[2*128];
    __shared__ float sh_mx[2], sh_inv[2];
    int tid = threadIdx.x;                   // 256
    const float* hn = g_hbuf[(t + 1) & 1];

    if (blockIdx.x < 128) {                  // ---- gem for step t+1 ----
        gem_block(hn, bconvh, sh_h, blockIdx.x, tid);
        return;
    }

    // ---- head for 2 batches ----
    int bs = tid >> 7;                       // batch slot 0/1
    int lt = tid & 127;
    int b = (blockIdx.x - 128)*2 + bs;

    for (int i = lt; i < 512; i += 128) sh_h2[bs*512 + i] = hn[b*512 + i];
    __syncthreads();

    float a = 0.f;
    #pragma unroll 8
    for (int k = 0; k < 512; k++)
        a += g_WpT[k*128 + lt] * sh_h2[bs*512 + k];
    float y = a + ((lt < 123) ? bfc[lt] : 0.f);
    sh_y[bs*128 + lt] = y;
    __syncthreads();

    if (lt < 32) {                           // pi softmax stats over y[3..23)
        float v = (lt >= 3 && lt < 23) ? sh_y[bs*128 + lt] : -1e30f;
        float m = v;
        #pragma unroll
        for (int o = 16; o; o >>= 1) m = fmaxf(m, __shfl_xor_sync(0xffffffffu, m, o));
        float e = (lt >= 3 && lt < 23) ? expf(v - m) : 0.f;
        float s = e;
        #pragma unroll
        for (int o = 16; o; o >>= 1) s += __shfl_xor_sync(0xffffffffu, s, o);
        if (lt == 0) { sh_mx[bs] = m; sh_inv[bs] = 1.f / s; }
    }
    __syncthreads();

    if (lt < 123) {
        int row = b*257 + t;
        if (lt < 3)        out[6*OFF + row*3 + lt] = y;                           // pen logits
        else if (lt < 23)  out[          row*20 + (lt-3)]   = expf(y - sh_mx[bs]) * sh_inv[bs];
        else if (lt < 43)  out[1*OFF +  row*20 + (lt-23)]  = y;                   // mu1
        else if (lt < 63)  out[2*OFF +  row*20 + (lt-43)]  = y;                   // mu2
        else if (lt < 83)  out[3*OFF +  row*20 + (lt-63)]  = expf(y);             // s1
        else if (lt < 103) out[4*OFF +  row*20 + (lt-83)]  = expf(y);             // s2
        else               out[5*OFF +  row*20 + (lt-103)] = tanhf(y);            // corr
    }
}

// ---------------- launcher ----------------
extern "C" void kernel_launch(void* const* d_in, const int* in_sizes, int n_in,
                              void* d_out, int out_size)
{
    const float* backbone = (const float*)d_in[0];
    const float* z        = (const float*)d_in[1];
    const float* sketch   = (const float*)d_in[2];
    const float* Whc      = (const float*)d_in[3];
    const float* bhc      = (const float*)d_in[4];
    const float* Wch      = (const float*)d_in[5];
    const float* bch      = (const float*)d_in[6];
    const float* Kconv    = (const float*)d_in[7];
    const float* bconvf   = (const float*)d_in[8];
    const float* Watt     = (const float*)d_in[9];
    const float* batt     = (const float*)d_in[10];
    const float* Wih      = (const float*)d_in[11];
    const float* Whh      = (const float*)d_in[12];
    const float* bih      = (const float*)d_in[13];
    const float* bhh      = (const float*)d_in[14];
    const float* Wp       = (const float*)d_in[15];
    const float* bfc      = (const float*)d_in[16];
    float* out = (float*)d_out;
    (void)in_sizes; (void)n_in; (void)out_size;

    pack_kernel<<<32768, 256>>>(Wih, Whh, Wch, Wp, Kconv, backbone);
    init_hc_kernel<<<64, 256>>>(z, Whc, bhc);
    conv_kernel<<<dim3(256, 4), 256>>>(backbone, bconvf);
    gem0_kernel<<<128, 256>>>(bch);

    for (int t = 0; t < TT; t++) {
        attn_kernel<<<256, 256>>>(Watt, batt, t);
        gates_kernel<<<dim3(8, 32), 256>>>(bih, bhh, sketch, t);
        head_gem_kernel<<<256, 256>>>(bfc, out, bch, t);
    }
}